// round 15
// baseline (speedup 1.0000x reference)
#include <cuda_runtime.h>
#include <cuda_bf16.h>
#include <mma.h>
#include <math.h>

using namespace nvcuda;

#define HIDDEN 128
#define MAX_ING 20000
#define MAX_CMP 10000

// Precomputed per-node projections in bf16 (L2-resident: 5MB + 2.5MB)
__device__ __nv_bfloat16 g_P_ing[MAX_ING * HIDDEN];
__device__ __nv_bfloat16 g_P_cmp[MAX_CMP * HIDDEN];

// ---------------------------------------------------------------------------
// proj v8: pipelined single-wave plain-bf16 wmma.
// CHUNKS_PER_BLOCK=4 -> 119 blocks (single wave on 148 SMs).
// Double-buffered A: next chunk's global X loads issue BEFORE this chunk's
// MMA, hiding the ~600cyc gmem latency. Non-aliased regions:
//   A0 [0,17408) | A1 [17408,34816) | W [34816,69632) | Cst [69632,102400)
// 100KB smem -> 2 blocks/SM co-resident.
// ---------------------------------------------------------------------------
#define A_LD 136
#define W_LD 136
#define SM_A_BYTES (64 * A_LD * 2)        // 17408
#define SM_W_BYTES (128 * W_LD * 2)       // 34816
#define OFF_A0 0
#define OFF_A1 SM_A_BYTES
#define OFF_W  (2 * SM_A_BYTES)
#define OFF_C  (2 * SM_A_BYTES + SM_W_BYTES)
#define PROJ_SMEM_BYTES (OFF_C + 64 * 128 * 4)   // 102400
#define CHUNKS_PER_BLOCK 4

// stage one 64x128 fp32 chunk as bf16 into Abuf (clamped rows)
__device__ __forceinline__ void stage_A(
    const float4* __restrict__ X4, __nv_bfloat16* __restrict__ Abuf,
    int row0, int nrows, int tid)
{
    #pragma unroll
    for (int i = 0; i < 8; i++) {
        const int v = tid + i * 256;   // 2048 float4 slots
        const int r = v >> 5;          // 0..63
        const int c4 = v & 31;
        const int rs = min(row0 + r, nrows - 1);
        const float4 x = X4[(size_t)rs * 32 + c4];
        __nv_bfloat162 lo = __float22bfloat162_rn(make_float2(x.x, x.y));
        __nv_bfloat162 hi = __float22bfloat162_rn(make_float2(x.z, x.w));
        uint2 o;
        o.x = *reinterpret_cast<unsigned int*>(&lo);
        o.y = *reinterpret_cast<unsigned int*>(&hi);
        *reinterpret_cast<uint2*>(&Abuf[r * A_LD + c4 * 4]) = o;
    }
}

__global__ void __launch_bounds__(256) proj_kernel(
    const float* __restrict__ x_ing,
    const float* __restrict__ x_cmp,
    const float* __restrict__ W1,
    const float* __restrict__ b1,
    int n_ing, int n_cmp, int blocks_ing)
{
    const bool is_cmp = (blockIdx.x >= blocks_ing);
    const float* __restrict__ X = is_cmp ? x_cmp : x_ing;
    const float* __restrict__ W = is_cmp ? (W1 + HIDDEN * HIDDEN) : W1;
    __nv_bfloat16* __restrict__ P = is_cmp ? g_P_cmp : g_P_ing;
    const int nrows = is_cmp ? n_cmp : n_ing;
    const int bid = is_cmp ? ((int)blockIdx.x - blocks_ing) : (int)blockIdx.x;
    const int nchunks = (nrows + 63) / 64;
    const int chunk0 = bid * CHUNKS_PER_BLOCK;
    if (chunk0 >= nchunks) return;

    const int tid = threadIdx.x;
    const int wid = tid >> 5;

    extern __shared__ __align__(16) char sm[];
    __nv_bfloat16* A_buf[2] = {
        reinterpret_cast<__nv_bfloat16*>(sm + OFF_A0),
        reinterpret_cast<__nv_bfloat16*>(sm + OFF_A1)
    };
    __nv_bfloat16* W_s = reinterpret_cast<__nv_bfloat16*>(sm + OFF_W);
    float* Cst = reinterpret_cast<float*>(sm + OFF_C);

    // --- stage W half (128x128 fp32 -> bf16): ONCE per block ---
    const float4* __restrict__ Wg4 = reinterpret_cast<const float4*>(W);
    #pragma unroll
    for (int i = 0; i < 16; i++) {
        const int v = tid + i * 256;       // 4096 float4 slots
        const int r = v >> 5;
        const int c4 = v & 31;
        const float4 w = Wg4[v];
        __nv_bfloat162 lo = __float22bfloat162_rn(make_float2(w.x, w.y));
        __nv_bfloat162 hi = __float22bfloat162_rn(make_float2(w.z, w.w));
        uint2 o;
        o.x = *reinterpret_cast<unsigned int*>(&lo);
        o.y = *reinterpret_cast<unsigned int*>(&hi);
        *reinterpret_cast<uint2*>(&W_s[r * W_LD + c4 * 4]) = o;
    }

    const float4* __restrict__ X4 = reinterpret_cast<const float4*>(X);
    const int warp_r = (wid & 3) * 16;
    const int warp_c = (wid >> 2) * 64;
    uint2* P2 = reinterpret_cast<uint2*>(P);

    // prologue: stage first chunk into buf0
    stage_A(X4, A_buf[0], chunk0 * 64, nrows, tid);
    __syncthreads();   // W + A0 visible

    #pragma unroll
    for (int cc = 0; cc < CHUNKS_PER_BLOCK; cc++) {
        const int chunk = chunk0 + cc;
        if (chunk >= nchunks) break;
        const int row0 = chunk * 64;
        const int cur = cc & 1;

        // prefetch next chunk into the other buffer (overlaps this MMA)
        if (cc + 1 < CHUNKS_PER_BLOCK && chunk + 1 < nchunks)
            stage_A(X4, A_buf[cur ^ 1], (chunk + 1) * 64, nrows, tid);

        // --- bf16 wmma: 16x64 per warp ---
        wmma::fragment<wmma::accumulator, 16, 16, 16, float> acc[4];
        #pragma unroll
        for (int c = 0; c < 4; c++) wmma::fill_fragment(acc[c], 0.f);

        #pragma unroll
        for (int k = 0; k < 8; k++) {
            wmma::fragment<wmma::matrix_a, 16, 16, 16, __nv_bfloat16, wmma::row_major> a;
            wmma::load_matrix_sync(a, &A_buf[cur][warp_r * A_LD + k * 16], A_LD);
            #pragma unroll
            for (int c = 0; c < 4; c++) {
                wmma::fragment<wmma::matrix_b, 16, 16, 16, __nv_bfloat16, wmma::row_major> b;
                wmma::load_matrix_sync(b, &W_s[(k * 16) * W_LD + warp_c + c * 16], W_LD);
                wmma::mma_sync(acc[c], a, b, acc[c]);
            }
        }

        #pragma unroll
        for (int c = 0; c < 4; c++)
            wmma::store_matrix_sync(&Cst[warp_r * 128 + warp_c + c * 16], acc[c],
                                    128, wmma::mem_row_major);
        __syncthreads();   // Cst complete; prefetch STS complete (next MMA safe)

        // --- bias (cmp) + bf16 convert + store ---
        #pragma unroll
        for (int i = 0; i < 8; i++) {
            const int v = tid + i * 256;
            const int r = v >> 5;
            const int c4 = v & 31;
            if (row0 + r < nrows) {
                float4 p = *reinterpret_cast<const float4*>(&Cst[r * 128 + c4 * 4]);
                if (is_cmp) {
                    const float4 bv = reinterpret_cast<const float4*>(b1)[c4];
                    p.x += bv.x; p.y += bv.y; p.z += bv.z; p.w += bv.w;
                }
                __nv_bfloat162 lo = __float22bfloat162_rn(make_float2(p.x, p.y));
                __nv_bfloat162 hi = __float22bfloat162_rn(make_float2(p.z, p.w));
                uint2 o;
                o.x = *reinterpret_cast<unsigned int*>(&lo);
                o.y = *reinterpret_cast<unsigned int*>(&hi);
                P2[(size_t)(row0 + r) * 32 + c4] = o;
            }
        }
        __syncthreads();   // Cst reads done before next chunk's store_matrix
    }
}

// ---------------------------------------------------------------------------
// Edge kernel (R8/R12-proven, byte-identical): 8 lanes/edge, 4 edges/group,
// contiguous 128B-line __ldcg gathers, bit-shift unpack, FFMA dot,
// 3-shuffle reduce, float4 store. Pinned at chip LTS byte floor — done.
// ---------------------------------------------------------------------------
__device__ __forceinline__ float edge_slice_dot(
    int s, int d, int t, const float* __restrict__ wv)
{
    const char* pa = (const char*)g_P_ing + (size_t)s * 256 + t * 16;
    const char* pb = (const char*)g_P_cmp + (size_t)d * 256 + t * 16;
    const uint4 al = __ldcg(reinterpret_cast<const uint4*>(pa));
    const uint4 ah = __ldcg(reinterpret_cast<const uint4*>(pa + 128));
    const uint4 bl = __ldcg(reinterpret_cast<const uint4*>(pb));
    const uint4 bh = __ldcg(reinterpret_cast<const uint4*>(pb + 128));

    const __nv_bfloat162 z2 = __float2bfloat162_rn(0.f);
    const unsigned av[8] = {al.x, al.y, al.z, al.w, ah.x, ah.y, ah.z, ah.w};
    const unsigned bv[8] = {bl.x, bl.y, bl.z, bl.w, bh.x, bh.y, bh.z, bh.w};

    float acc = 0.f;
    #pragma unroll
    for (int j = 0; j < 8; j++) {
        __nv_bfloat162 ha = *reinterpret_cast<const __nv_bfloat162*>(&av[j]);
        __nv_bfloat162 hb = *reinterpret_cast<const __nv_bfloat162*>(&bv[j]);
        __nv_bfloat162 h2 = __hmax2(__hadd2(ha, hb), z2);
        const unsigned hu = *reinterpret_cast<const unsigned*>(&h2);
        acc = fmaf(__uint_as_float(hu << 16),         wv[2 * j],     acc);
        acc = fmaf(__uint_as_float(hu & 0xFFFF0000u), wv[2 * j + 1], acc);
    }
    return acc;
}

__global__ void __launch_bounds__(256, 6) edge_kernel(
    const int* __restrict__ ei,
    const float* __restrict__ W2,
    const float* __restrict__ b2,
    float* __restrict__ out,
    int E)
{
    const int gid = (blockIdx.x * 256 + threadIdx.x) >> 3;
    const int t = threadIdx.x & 7;
    const int e0 = gid * 4;
    if (e0 >= E) return;

    const float4* W24 = reinterpret_cast<const float4*>(W2);
    const float4 wl0 = __ldg(W24 + 2 * t + 0);
    const float4 wl1 = __ldg(W24 + 2 * t + 1);
    const float4 wh0 = __ldg(W24 + 16 + 2 * t + 0);
    const float4 wh1 = __ldg(W24 + 16 + 2 * t + 1);
    const float wv[16] = {wl0.x, wl0.y, wl0.z, wl0.w,
                          wl1.x, wl1.y, wl1.z, wl1.w,
                          wh0.x, wh0.y, wh0.z, wh0.w,
                          wh1.x, wh1.y, wh1.z, wh1.w};
    const float b2v = __ldg(b2);

    int sv[4], dv[4];
    int ne;
    if (e0 + 4 <= E) {
        ne = 4;
        const int4 s4 = __ldg(reinterpret_cast<const int4*>(ei + e0));
        const int4 d4 = __ldg(reinterpret_cast<const int4*>(ei + E + e0));
        sv[0] = s4.x; sv[1] = s4.y; sv[2] = s4.z; sv[3] = s4.w;
        dv[0] = d4.x; dv[1] = d4.y; dv[2] = d4.z; dv[3] = d4.w;
    } else {
        ne = E - e0;
        for (int i = 0; i < ne; i++) {
            sv[i] = __ldg(ei + e0 + i);
            dv[i] = __ldg(ei + E + e0 + i);
        }
        for (int i = ne; i < 4; i++) { sv[i] = 0; dv[i] = 0; }
    }

    float acc[4];
    #pragma unroll
    for (int i = 0; i < 4; i++)
        acc[i] = edge_slice_dot(sv[i], dv[i], t, wv);

    #pragma unroll
    for (int i = 0; i < 4; i++) {
        acc[i] += __shfl_xor_sync(0xFFFFFFFFu, acc[i], 1);
        acc[i] += __shfl_xor_sync(0xFFFFFFFFu, acc[i], 2);
        acc[i] += __shfl_xor_sync(0xFFFFFFFFu, acc[i], 4);
    }

    if (t == 0) {
        if (ne == 4) {
            float4 o;
            o.x = 1.f / (1.f + __expf(-(acc[0] + b2v)));
            o.y = 1.f / (1.f + __expf(-(acc[1] + b2v)));
            o.z = 1.f / (1.f + __expf(-(acc[2] + b2v)));
            o.w = 1.f / (1.f + __expf(-(acc[3] + b2v)));
            *reinterpret_cast<float4*>(out + e0) = o;
        } else {
            for (int i = 0; i < ne; i++)
                out[e0 + i] = 1.f / (1.f + __expf(-(acc[i] + b2v)));
        }
    }
}

extern "C" void kernel_launch(void* const* d_in, const int* in_sizes, int n_in,
                              void* d_out, int out_size)
{
    const float* x_ing = (const float*)d_in[0];
    const float* x_cmp = (const float*)d_in[1];
    const int*   ei    = (const int*)d_in[2];
    const float* W1    = (const float*)d_in[3];
    const float* b1    = (const float*)d_in[4];
    const float* W2    = (const float*)d_in[5];
    const float* b2    = (const float*)d_in[6];
    float* out = (float*)d_out;

    const int n_ing = in_sizes[0] / HIDDEN;
    const int n_cmp = in_sizes[1] / HIDDEN;
    const int E     = in_sizes[2] / 2;

    cudaFuncSetAttribute(proj_kernel,
                         cudaFuncAttributeMaxDynamicSharedMemorySize,
                         PROJ_SMEM_BYTES);

    const int nch_ing = (n_ing + 63) / 64;
    const int nch_cmp = (n_cmp + 63) / 64;
    const int blocks_ing = (nch_ing + CHUNKS_PER_BLOCK - 1) / CHUNKS_PER_BLOCK;
    const int blocks_cmp = (nch_cmp + CHUNKS_PER_BLOCK - 1) / CHUNKS_PER_BLOCK;
    proj_kernel<<<blocks_ing + blocks_cmp, 256, PROJ_SMEM_BYTES>>>(
        x_ing, x_cmp, W1, b1, n_ing, n_cmp, blocks_ing);

    const int blocks = (E + 127) / 128;  // 128 edges per 256-thread block
    edge_kernel<<<blocks, 256>>>(ei, W2, b2, out, E);
}

// round 16
// speedup vs baseline: 1.1047x; 1.1047x over previous
#include <cuda_runtime.h>
#include <cuda_bf16.h>
#include <mma.h>
#include <math.h>

using namespace nvcuda;

#define HIDDEN 128
#define MAX_ING 20000
#define MAX_CMP 10000

// Precomputed per-node projections in bf16 (L2-resident: 5MB + 2.5MB)
__device__ __nv_bfloat16 g_P_ing[MAX_ING * HIDDEN];
__device__ __nv_bfloat16 g_P_cmp[MAX_CMP * HIDDEN];

// ---------------------------------------------------------------------------
// proj (R12-exact, proven 62.0us total): single-pass plain-bf16 wmma.
// P = X @ W (+bias for cmp). A (64x128) and W half (128x128) fp32->bf16 into
// smem once per block; 1 MMA per (k,c). smem 52224B -> high occupancy.
// ---------------------------------------------------------------------------
#define A_LD 136
#define W_LD 136
#define SM_A_ELEMS (64 * A_LD)
#define SM_W_ELEMS (128 * W_LD)
#define PROJ_SMEM_BYTES ((SM_A_ELEMS + SM_W_ELEMS) * 2)   // 52224

__global__ void __launch_bounds__(256) proj_kernel(
    const float* __restrict__ x_ing,
    const float* __restrict__ x_cmp,
    const float* __restrict__ W1,
    const float* __restrict__ b1,
    int n_ing, int n_cmp, int blocks_ing)
{
    const bool is_cmp = (blockIdx.x >= blocks_ing);
    const float* __restrict__ X = is_cmp ? x_cmp : x_ing;
    const float* __restrict__ W = is_cmp ? (W1 + HIDDEN * HIDDEN) : W1;
    __nv_bfloat16* __restrict__ P = is_cmp ? g_P_cmp : g_P_ing;
    const int nrows = is_cmp ? n_cmp : n_ing;
    const int bid = is_cmp ? ((int)blockIdx.x - blocks_ing) : (int)blockIdx.x;

    const int row0 = bid * 64;
    const int tid = threadIdx.x;
    const int wid = tid >> 5;

    extern __shared__ __align__(16) char sm[];
    __nv_bfloat16* A_s = reinterpret_cast<__nv_bfloat16*>(sm);
    __nv_bfloat16* W_s = A_s + SM_A_ELEMS;
    float* Cst = reinterpret_cast<float*>(sm);   // reused after MMA loop

    // --- stage W half (128x128 fp32 -> bf16) ---
    const float4* __restrict__ Wg4 = reinterpret_cast<const float4*>(W);
    #pragma unroll
    for (int i = 0; i < 16; i++) {
        const int v = tid + i * 256;       // 4096 float4 slots
        const int r = v >> 5;
        const int c4 = v & 31;
        const float4 w = Wg4[v];
        __nv_bfloat162 lo = __float22bfloat162_rn(make_float2(w.x, w.y));
        __nv_bfloat162 hi = __float22bfloat162_rn(make_float2(w.z, w.w));
        uint2 o;
        o.x = *reinterpret_cast<unsigned int*>(&lo);
        o.y = *reinterpret_cast<unsigned int*>(&hi);
        *reinterpret_cast<uint2*>(&W_s[r * W_LD + c4 * 4]) = o;
    }

    // --- stage A tile (64x128 fp32 -> bf16, clamped rows) ---
    const float4* __restrict__ X4 = reinterpret_cast<const float4*>(X);
    #pragma unroll
    for (int i = 0; i < 8; i++) {
        const int v = tid + i * 256;       // 2048 float4 slots
        const int r = v >> 5;              // 0..63
        const int c4 = v & 31;
        const int rs = min(row0 + r, nrows - 1);
        const float4 x = X4[(size_t)rs * 32 + c4];
        __nv_bfloat162 lo = __float22bfloat162_rn(make_float2(x.x, x.y));
        __nv_bfloat162 hi = __float22bfloat162_rn(make_float2(x.z, x.w));
        uint2 o;
        o.x = *reinterpret_cast<unsigned int*>(&lo);
        o.y = *reinterpret_cast<unsigned int*>(&hi);
        *reinterpret_cast<uint2*>(&A_s[r * A_LD + c4 * 4]) = o;
    }
    __syncthreads();

    // --- bf16 wmma mainloop: 16x64 per warp, 1 MMA per (k,c) ---
    const int warp_r = (wid & 3) * 16;
    const int warp_c = (wid >> 2) * 64;

    wmma::fragment<wmma::accumulator, 16, 16, 16, float> acc[4];
    #pragma unroll
    for (int c = 0; c < 4; c++) wmma::fill_fragment(acc[c], 0.f);

    #pragma unroll
    for (int k = 0; k < 8; k++) {
        wmma::fragment<wmma::matrix_a, 16, 16, 16, __nv_bfloat16, wmma::row_major> a;
        wmma::load_matrix_sync(a, &A_s[warp_r * A_LD + k * 16], A_LD);
        #pragma unroll
        for (int c = 0; c < 4; c++) {
            wmma::fragment<wmma::matrix_b, 16, 16, 16, __nv_bfloat16, wmma::row_major> b;
            wmma::load_matrix_sync(b, &W_s[(k * 16) * W_LD + warp_c + c * 16], W_LD);
            wmma::mma_sync(acc[c], a, b, acc[c]);
        }
    }
    __syncthreads();   // all MMA smem reads done before Cst overwrite

    #pragma unroll
    for (int c = 0; c < 4; c++)
        wmma::store_matrix_sync(&Cst[warp_r * 128 + warp_c + c * 16], acc[c],
                                128, wmma::mem_row_major);
    __syncthreads();

    // --- bias (cmp) + bf16 convert + store ---
    uint2* P2 = reinterpret_cast<uint2*>(P);
    #pragma unroll
    for (int i = 0; i < 8; i++) {
        const int v = tid + i * 256;
        const int r = v >> 5;
        const int c4 = v & 31;
        if (row0 + r < nrows) {
            float4 p = *reinterpret_cast<const float4*>(&Cst[r * 128 + c4 * 4]);
            if (is_cmp) {
                const float4 bv = reinterpret_cast<const float4*>(b1)[c4];
                p.x += bv.x; p.y += bv.y; p.z += bv.z; p.w += bv.w;
            }
            __nv_bfloat162 lo = __float22bfloat162_rn(make_float2(p.x, p.y));
            __nv_bfloat162 hi = __float22bfloat162_rn(make_float2(p.z, p.w));
            uint2 o;
            o.x = *reinterpret_cast<unsigned int*>(&lo);
            o.y = *reinterpret_cast<unsigned int*>(&hi);
            P2[(size_t)(row0 + r) * 32 + c4] = o;
        }
    }
}

// ---------------------------------------------------------------------------
// Edge kernel v8: R12 body + grid-stride x2 — halves block count and
// amortizes per-thread setup (W2/b2 loads, lane math) over 2 groups.
// Gathers/math byte-identical to the proven LTS-capped version.
// ---------------------------------------------------------------------------
#define EDGE_ITERS 2

__device__ __forceinline__ float edge_slice_dot(
    int s, int d, int t, const float* __restrict__ wv)
{
    const char* pa = (const char*)g_P_ing + (size_t)s * 256 + t * 16;
    const char* pb = (const char*)g_P_cmp + (size_t)d * 256 + t * 16;
    const uint4 al = __ldcg(reinterpret_cast<const uint4*>(pa));
    const uint4 ah = __ldcg(reinterpret_cast<const uint4*>(pa + 128));
    const uint4 bl = __ldcg(reinterpret_cast<const uint4*>(pb));
    const uint4 bh = __ldcg(reinterpret_cast<const uint4*>(pb + 128));

    const __nv_bfloat162 z2 = __float2bfloat162_rn(0.f);
    const unsigned av[8] = {al.x, al.y, al.z, al.w, ah.x, ah.y, ah.z, ah.w};
    const unsigned bv[8] = {bl.x, bl.y, bl.z, bl.w, bh.x, bh.y, bh.z, bh.w};

    float acc = 0.f;
    #pragma unroll
    for (int j = 0; j < 8; j++) {
        __nv_bfloat162 ha = *reinterpret_cast<const __nv_bfloat162*>(&av[j]);
        __nv_bfloat162 hb = *reinterpret_cast<const __nv_bfloat162*>(&bv[j]);
        __nv_bfloat162 h2 = __hmax2(__hadd2(ha, hb), z2);
        const unsigned hu = *reinterpret_cast<const unsigned*>(&h2);
        acc = fmaf(__uint_as_float(hu << 16),         wv[2 * j],     acc);
        acc = fmaf(__uint_as_float(hu & 0xFFFF0000u), wv[2 * j + 1], acc);
    }
    return acc;
}

__global__ void __launch_bounds__(256, 6) edge_kernel(
    const int* __restrict__ ei,
    const float* __restrict__ W2,
    const float* __restrict__ b2,
    float* __restrict__ out,
    int E)
{
    const int t = threadIdx.x & 7;

    // per-thread setup, paid once for EDGE_ITERS groups
    const float4* W24 = reinterpret_cast<const float4*>(W2);
    const float4 wl0 = __ldg(W24 + 2 * t + 0);
    const float4 wl1 = __ldg(W24 + 2 * t + 1);
    const float4 wh0 = __ldg(W24 + 16 + 2 * t + 0);
    const float4 wh1 = __ldg(W24 + 16 + 2 * t + 1);
    const float wv[16] = {wl0.x, wl0.y, wl0.z, wl0.w,
                          wl1.x, wl1.y, wl1.z, wl1.w,
                          wh0.x, wh0.y, wh0.z, wh0.w,
                          wh1.x, wh1.y, wh1.z, wh1.w};
    const float b2v = __ldg(b2);

    const int ngroups = (E + 3) >> 2;
    const int gstride = (gridDim.x * 256) >> 3;
    int gid = (blockIdx.x * 256 + threadIdx.x) >> 3;

    #pragma unroll
    for (int it = 0; it < EDGE_ITERS; it++, gid += gstride) {
        if (gid >= ngroups) break;
        const int e0 = gid * 4;

        int sv[4], dv[4];
        int ne;
        if (e0 + 4 <= E) {
            ne = 4;
            const int4 s4 = __ldg(reinterpret_cast<const int4*>(ei + e0));
            const int4 d4 = __ldg(reinterpret_cast<const int4*>(ei + E + e0));
            sv[0] = s4.x; sv[1] = s4.y; sv[2] = s4.z; sv[3] = s4.w;
            dv[0] = d4.x; dv[1] = d4.y; dv[2] = d4.z; dv[3] = d4.w;
        } else {
            ne = E - e0;
            for (int i = 0; i < ne; i++) {
                sv[i] = __ldg(ei + e0 + i);
                dv[i] = __ldg(ei + E + e0 + i);
            }
            for (int i = ne; i < 4; i++) { sv[i] = 0; dv[i] = 0; }
        }

        float acc[4];
        #pragma unroll
        for (int i = 0; i < 4; i++)
            acc[i] = edge_slice_dot(sv[i], dv[i], t, wv);

        #pragma unroll
        for (int i = 0; i < 4; i++) {
            acc[i] += __shfl_xor_sync(0xFFFFFFFFu, acc[i], 1);
            acc[i] += __shfl_xor_sync(0xFFFFFFFFu, acc[i], 2);
            acc[i] += __shfl_xor_sync(0xFFFFFFFFu, acc[i], 4);
        }

        if (t == 0) {
            if (ne == 4) {
                float4 o;
                o.x = 1.f / (1.f + __expf(-(acc[0] + b2v)));
                o.y = 1.f / (1.f + __expf(-(acc[1] + b2v)));
                o.z = 1.f / (1.f + __expf(-(acc[2] + b2v)));
                o.w = 1.f / (1.f + __expf(-(acc[3] + b2v)));
                *reinterpret_cast<float4*>(out + e0) = o;
            } else {
                for (int i = 0; i < ne; i++)
                    out[e0 + i] = 1.f / (1.f + __expf(-(acc[i] + b2v)));
            }
        }
    }
}

extern "C" void kernel_launch(void* const* d_in, const int* in_sizes, int n_in,
                              void* d_out, int out_size)
{
    const float* x_ing = (const float*)d_in[0];
    const float* x_cmp = (const float*)d_in[1];
    const int*   ei    = (const int*)d_in[2];
    const float* W1    = (const float*)d_in[3];
    const float* b1    = (const float*)d_in[4];
    const float* W2    = (const float*)d_in[5];
    const float* b2    = (const float*)d_in[6];
    float* out = (float*)d_out;

    const int n_ing = in_sizes[0] / HIDDEN;
    const int n_cmp = in_sizes[1] / HIDDEN;
    const int E     = in_sizes[2] / 2;

    cudaFuncSetAttribute(proj_kernel,
                         cudaFuncAttributeMaxDynamicSharedMemorySize,
                         PROJ_SMEM_BYTES);

    const int blocks_ing = (n_ing + 63) / 64;
    const int blocks_cmp = (n_cmp + 63) / 64;
    proj_kernel<<<blocks_ing + blocks_cmp, 256, PROJ_SMEM_BYTES>>>(
        x_ing, x_cmp, W1, b1, n_ing, n_cmp, blocks_ing);

    // 32 groups/block * EDGE_ITERS groups per thread-group
    const int ngroups = (E + 3) / 4;
    const int blocks = (ngroups + 32 * EDGE_ITERS - 1) / (32 * EDGE_ITERS);
    edge_kernel<<<blocks, 256>>>(ei, W2, b2, out, E);
}